// round 7
// baseline (speedup 1.0000x reference)
#include <cuda_runtime.h>

// ---------------------------------------------------------------------------
// 256-bin histogram of 33.5M fp32 in [0,255] + count = batchsize*hist[0].
//
// R7: issue-bound -> minimize instructions/element.
//   bin+addr fused:  u = bits(fmaf_rz(x, 256/255, 2^23)) = 0x4B000000 + bin
//                    addr = u*128 + (lanoff + 0x80000000)  (mod 2^32)
//                         = bin*128 + lanoff     [1 FFMA + 1 IMAD, no mask/clamp]
//   ACC4 collision correction (6 compares / 4 elems) instead of ACC8 (28/8).
//   u8 per-thread-column counters, conflict-free banks, 7 blocks/SM, 1 wave,
//   fused last-block finalize (idempotent for graph replay).
// ---------------------------------------------------------------------------

#define TPB        128
#define SBINS      257                      // 256 bins + spill (unused, safety)
#define WPB        32                       // 32-bit words per bin (128 u8 cols)
#define SMEM_WORDS (SBINS * WPB)            // 32896 bytes
#define NBLK       1064                     // 152 SMs * 7 -> one wave

__device__ unsigned int g_hist[256];
__device__ unsigned int g_done;

#define BINC   1.00392156862745f            /* 256/255 */
#define FBIAS  8388608.0f                   /* 2^23 */

// fused bin+address: returns bin*128 + lanoff (lanoff2 carries +0x80000000)
__device__ __forceinline__ unsigned badr(float x, unsigned lanoff2) {
    unsigned u = __float_as_uint(__fmaf_rz(x, BINC, FBIAS));
    return u * 128u + lanoff2;              // wraps: 0x4B000000*128 ≡ 0x80000000
}

// 4 elements of one lane: 4 batched LDS.U8, exact collision correction
// (equal bins <=> equal addresses), 4 ordered STS.U8.
__device__ __forceinline__ void acc4(unsigned char* sh8, unsigned lanoff2, float4 x) {
    unsigned a0 = badr(x.x, lanoff2), a1 = badr(x.y, lanoff2);
    unsigned a2 = badr(x.z, lanoff2), a3 = badr(x.w, lanoff2);
    unsigned c0 = sh8[a0], c1 = sh8[a1], c2 = sh8[a2], c3 = sh8[a3];
    c0 += 1u;
    c1 += 1u + (a1 == a0);
    c2 += 1u + (a2 == a0) + (a2 == a1);
    c3 += 1u + (a3 == a0) + (a3 == a1) + (a3 == a2);
    sh8[a0] = (unsigned char)c0;
    sh8[a1] = (unsigned char)c1;
    sh8[a2] = (unsigned char)c2;
    sh8[a3] = (unsigned char)c3;
}

__global__ void __launch_bounds__(TPB, 7)
hist_kernel(const float* __restrict__ inf, const int* __restrict__ bsz,
            float* __restrict__ out, int n) {
    __shared__ unsigned int sh[SMEM_WORDS];
    const int t = threadIdx.x;

    #pragma unroll 4
    for (int i = t; i < SMEM_WORDS; i += TPB) sh[i] = 0u;
    __syncthreads();

    unsigned char* sh8 = (unsigned char*)sh;
    const unsigned lanoff2 = (((t & 31) << 2) | (t >> 5)) + 0x80000000u;

    const int n4 = n >> 2;
    const float4* __restrict__ in4 = (const float4*)inf;
    const int S = gridDim.x * TPB;
    int i = blockIdx.x * TPB + t;

    // flat loop: 8 LDG.128 batched up front (MLP), then 8x acc4
    for (; i + 7 * S < n4; i += 8 * S) {
        float4 v0 = in4[i];
        float4 v1 = in4[i + S];
        float4 v2 = in4[i + 2 * S];
        float4 v3 = in4[i + 3 * S];
        float4 v4 = in4[i + 4 * S];
        float4 v5 = in4[i + 5 * S];
        float4 v6 = in4[i + 6 * S];
        float4 v7 = in4[i + 7 * S];
        acc4(sh8, lanoff2, v0);
        acc4(sh8, lanoff2, v1);
        acc4(sh8, lanoff2, v2);
        acc4(sh8, lanoff2, v3);
        acc4(sh8, lanoff2, v4);
        acc4(sh8, lanoff2, v5);
        acc4(sh8, lanoff2, v6);
        acc4(sh8, lanoff2, v7);
    }
    for (; i < n4; i += S)
        acc4(sh8, lanoff2, in4[i]);
    if (blockIdx.x == 0 && t < (n & 3)) {      // scalar tail
        unsigned a = badr(inf[(n4 << 2) + t], lanoff2);
        sh8[a] = (unsigned char)(sh8[a] + 1);
    }
    __syncthreads();

    // per-bin byte-sum via dp4a; one global atomic per bin per block
    for (int b = t; b < 256; b += TPB) {
        unsigned int s = 0;
        #pragma unroll 8
        for (int k = 0; k < WPB; k++)
            s = __dp4a(sh[b * WPB + ((k + t) & (WPB - 1))], 0x01010101u, s);
        atomicAdd(&g_hist[b], s);
    }

    // last arriving block finalizes and resets state (idempotent replays)
    __shared__ unsigned int is_last;
    __shared__ float h0s;
    __threadfence();
    if (t == 0) {
        unsigned ticket = atomicAdd(&g_done, 1u);
        is_last = (ticket == (unsigned)(gridDim.x - 1));
    }
    __syncthreads();
    if (is_last) {
        __threadfence();
        if (t == 0) { h0s = (float)g_hist[0]; g_done = 0u; }
        __syncthreads();
        float c = (float)(*bsz) * h0s;
        #pragma unroll
        for (int b = t; b < 256; b += TPB) {
            out[b]       = (float)g_hist[b];
            out[256 + b] = c;
        }
        __syncthreads();
        #pragma unroll
        for (int b = t; b < 256; b += TPB) g_hist[b] = 0u;
    }
}

extern "C" void kernel_launch(void* const* d_in, const int* in_sizes, int n_in,
                              void* d_out, int out_size) {
    const float* x;
    const int*   bs;
    int n;
    if (n_in >= 2 && in_sizes[0] >= in_sizes[1]) {
        x = (const float*)d_in[0]; bs = (const int*)d_in[1]; n = in_sizes[0];
    } else {
        x = (const float*)d_in[1]; bs = (const int*)d_in[0]; n = in_sizes[1];
    }
    hist_kernel<<<NBLK, TPB>>>(x, bs, (float*)d_out, n);
}

// round 9
// speedup vs baseline: 1.2143x; 1.2143x over previous
#include <cuda_runtime.h>

// ---------------------------------------------------------------------------
// 256-bin histogram of 33.5M fp32 in [0,255] + count = batchsize*hist[0].
//
// R8: pipe-balanced ACC8.
//   - fused bin+addr: bits(fmaf_rz(x,256/255,2^23))*128 + lanoff2  (1 FFMA +
//     1 IMAD; no LOP3 mask, no IMNMX clamp)
//   - collision corrections compare FLOAT fma results (FSETP -> FMA pipe)
//     instead of ints, balancing fma/alu issue (R5 capped on ALU @42.8%).
//   - ACC8 batch keeps 8 LDS in flight (R7 proved 4 is too shallow).
//   u8 per-thread-column counters, conflict-free banks, 6 blocks/SM, 1 wave,
//   fused last-block finalize (idempotent for graph replay).
// ---------------------------------------------------------------------------

#define TPB        128
#define SBINS      257
#define WPB        32                       // words per bin (128 u8 columns)
#define SMEM_WORDS (SBINS * WPB)            // 32896 bytes
#define NBLK       912                      // 152 SMs * 6 -> one wave

__device__ unsigned int g_hist[256];
__device__ unsigned int g_done;

#define BINC   1.00392156862745f            /* 256/255 */
#define FBIAS  8388608.0f                   /* 2^23 */

// 8 elements of one lane: 8 batched LDS.U8, FSETP-based collision
// correction (fma pipe), 8 ordered STS.U8.
__device__ __forceinline__ void acc8(unsigned char* sh8, unsigned lanoff2,
                                     float4 u, float4 v) {
    float f0 = __fmaf_rz(u.x, BINC, FBIAS), f1 = __fmaf_rz(u.y, BINC, FBIAS);
    float f2 = __fmaf_rz(u.z, BINC, FBIAS), f3 = __fmaf_rz(u.w, BINC, FBIAS);
    float f4 = __fmaf_rz(v.x, BINC, FBIAS), f5 = __fmaf_rz(v.y, BINC, FBIAS);
    float f6 = __fmaf_rz(v.z, BINC, FBIAS), f7 = __fmaf_rz(v.w, BINC, FBIAS);

    unsigned a0 = __float_as_uint(f0) * 128u + lanoff2;
    unsigned a1 = __float_as_uint(f1) * 128u + lanoff2;
    unsigned a2 = __float_as_uint(f2) * 128u + lanoff2;
    unsigned a3 = __float_as_uint(f3) * 128u + lanoff2;
    unsigned a4 = __float_as_uint(f4) * 128u + lanoff2;
    unsigned a5 = __float_as_uint(f5) * 128u + lanoff2;
    unsigned a6 = __float_as_uint(f6) * 128u + lanoff2;
    unsigned a7 = __float_as_uint(f7) * 128u + lanoff2;

    unsigned c0 = sh8[a0], c1 = sh8[a1], c2 = sh8[a2], c3 = sh8[a3];
    unsigned c4 = sh8[a4], c5 = sh8[a5], c6 = sh8[a6], c7 = sh8[a7];

    // float equality == bin equality (f = 2^23 + bin exactly, never NaN)
    c0 += 1u;
    c1 += 1u + (f1 == f0);
    c2 += 1u + (f2 == f0) + (f2 == f1);
    c3 += 1u + (f3 == f0) + (f3 == f1) + (f3 == f2);
    c4 += 1u + (f4 == f0) + (f4 == f1) + (f4 == f2) + (f4 == f3);
    c5 += 1u + (f5 == f0) + (f5 == f1) + (f5 == f2) + (f5 == f3) + (f5 == f4);
    c6 += 1u + (f6 == f0) + (f6 == f1) + (f6 == f2) + (f6 == f3) + (f6 == f4)
             + (f6 == f5);
    c7 += 1u + (f7 == f0) + (f7 == f1) + (f7 == f2) + (f7 == f3) + (f7 == f4)
             + (f7 == f5) + (f7 == f6);

    sh8[a0] = (unsigned char)c0; sh8[a1] = (unsigned char)c1;
    sh8[a2] = (unsigned char)c2; sh8[a3] = (unsigned char)c3;
    sh8[a4] = (unsigned char)c4; sh8[a5] = (unsigned char)c5;
    sh8[a6] = (unsigned char)c6; sh8[a7] = (unsigned char)c7;
}

__global__ void __launch_bounds__(TPB, 6)
hist_kernel(const float* __restrict__ inf, const int* __restrict__ bsz,
            float* __restrict__ out, int n) {
    __shared__ unsigned int sh[SMEM_WORDS];
    const int t = threadIdx.x;

    #pragma unroll 4
    for (int i = t; i < SMEM_WORDS; i += TPB) sh[i] = 0u;
    __syncthreads();

    unsigned char* sh8 = (unsigned char*)sh;
    // +0x80000000 cancels bits(2^23)*128 mod 2^32 -> addr = bin*128 + lanoff
    const unsigned lanoff2 = (((t & 31) << 2) | (t >> 5)) + 0x80000000u;

    const int n4 = n >> 2;
    const float4* __restrict__ in4 = (const float4*)inf;
    const int S = gridDim.x * TPB;
    int i = blockIdx.x * TPB + t;

    for (; i + 7 * S < n4; i += 8 * S) {
        float4 v0 = in4[i];
        float4 v1 = in4[i + S];
        float4 v2 = in4[i + 2 * S];
        float4 v3 = in4[i + 3 * S];
        float4 v4 = in4[i + 4 * S];
        float4 v5 = in4[i + 5 * S];
        float4 v6 = in4[i + 6 * S];
        float4 v7 = in4[i + 7 * S];
        acc8(sh8, lanoff2, v0, v1);
        acc8(sh8, lanoff2, v2, v3);
        acc8(sh8, lanoff2, v4, v5);
        acc8(sh8, lanoff2, v6, v7);
    }
    for (; i < n4; i += S) {                   // float4 remainder
        float4 x = in4[i];
        float f0 = __fmaf_rz(x.x, BINC, FBIAS), f1 = __fmaf_rz(x.y, BINC, FBIAS);
        float f2 = __fmaf_rz(x.z, BINC, FBIAS), f3 = __fmaf_rz(x.w, BINC, FBIAS);
        unsigned a0 = __float_as_uint(f0) * 128u + lanoff2;
        unsigned a1 = __float_as_uint(f1) * 128u + lanoff2;
        unsigned a2 = __float_as_uint(f2) * 128u + lanoff2;
        unsigned a3 = __float_as_uint(f3) * 128u + lanoff2;
        unsigned c0 = sh8[a0], c1 = sh8[a1], c2 = sh8[a2], c3 = sh8[a3];
        c0 += 1u;
        c1 += 1u + (f1 == f0);
        c2 += 1u + (f2 == f0) + (f2 == f1);
        c3 += 1u + (f3 == f0) + (f3 == f1) + (f3 == f2);
        sh8[a0] = (unsigned char)c0; sh8[a1] = (unsigned char)c1;
        sh8[a2] = (unsigned char)c2; sh8[a3] = (unsigned char)c3;
    }
    if (blockIdx.x == 0 && t < (n & 3)) {      // scalar tail
        unsigned a = __float_as_uint(__fmaf_rz(inf[(n4 << 2) + t], BINC, FBIAS))
                     * 128u + lanoff2;
        sh8[a] = (unsigned char)(sh8[a] + 1);
    }
    __syncthreads();

    // per-bin byte-sum via dp4a; one global atomic per bin per block
    for (int b = t; b < 256; b += TPB) {
        unsigned int s = 0;
        #pragma unroll 8
        for (int k = 0; k < WPB; k++)
            s = __dp4a(sh[b * WPB + ((k + t) & (WPB - 1))], 0x01010101u, s);
        atomicAdd(&g_hist[b], s);
    }

    // last arriving block finalizes and resets state (idempotent replays)
    __shared__ unsigned int is_last;
    __shared__ float h0s;
    __threadfence();
    if (t == 0) {
        unsigned ticket = atomicAdd(&g_done, 1u);
        is_last = (ticket == (unsigned)(gridDim.x - 1));
    }
    __syncthreads();
    if (is_last) {
        __threadfence();
        if (t == 0) { h0s = (float)g_hist[0]; g_done = 0u; }
        __syncthreads();
        float c = (float)(*bsz) * h0s;
        #pragma unroll
        for (int b = t; b < 256; b += TPB) {
            out[b]       = (float)g_hist[b];
            out[256 + b] = c;
        }
        __syncthreads();
        #pragma unroll
        for (int b = t; b < 256; b += TPB) g_hist[b] = 0u;
    }
}

extern "C" void kernel_launch(void* const* d_in, const int* in_sizes, int n_in,
                              void* d_out, int out_size) {
    const float* x;
    const int*   bs;
    int n;
    if (n_in >= 2 && in_sizes[0] >= in_sizes[1]) {
        x = (const float*)d_in[0]; bs = (const int*)d_in[1]; n = in_sizes[0];
    } else {
        x = (const float*)d_in[1]; bs = (const int*)d_in[0]; n = in_sizes[1];
    }
    hist_kernel<<<NBLK, TPB>>>(x, bs, (float*)d_out, n);
}

// round 10
// speedup vs baseline: 1.2796x; 1.0538x over previous
#include <cuda_runtime.h>

// ---------------------------------------------------------------------------
// 256-bin histogram of 33.5M fp32 in [0,255] + count = batchsize*hist[0].
//
// R9: bounded continuous MLP. The 8-deep LDG.128 bursts overflowed the
// per-SM L1tex wavefront queue (24 warps x 8 LDG x 4 lines = 768 >> 248),
// serializing loads. Now a 1-stage ping-pong keeps exactly 2 LDG.128/warp
// in flight at all times (24 x 2 x 4 = 192 < 248). Binning/accumulate is
// the proven R8 scheme: fused FFMA bin+addr, FSETP collision correction,
// ACC8 u8 per-thread columns, 6 blocks/SM, one wave, fused finalize.
// ---------------------------------------------------------------------------

#define TPB        128
#define SBINS      257
#define WPB        32                       // words per bin (128 u8 columns)
#define SMEM_WORDS (SBINS * WPB)            // 32896 bytes
#define NBLK       912                      // 152 SMs * 6 -> one wave

__device__ unsigned int g_hist[256];
__device__ unsigned int g_done;

#define BINC   1.00392156862745f            /* 256/255 */
#define FBIAS  8388608.0f                   /* 2^23 */

// 8 elements of one lane: 8 batched LDS.U8, FSETP collision correction
// (fma pipe; f = 2^23+bin exactly, equality <=> same bin), 8 ordered STS.U8.
__device__ __forceinline__ void acc8(unsigned char* sh8, unsigned lanoff2,
                                     float4 u, float4 v) {
    float f0 = __fmaf_rz(u.x, BINC, FBIAS), f1 = __fmaf_rz(u.y, BINC, FBIAS);
    float f2 = __fmaf_rz(u.z, BINC, FBIAS), f3 = __fmaf_rz(u.w, BINC, FBIAS);
    float f4 = __fmaf_rz(v.x, BINC, FBIAS), f5 = __fmaf_rz(v.y, BINC, FBIAS);
    float f6 = __fmaf_rz(v.z, BINC, FBIAS), f7 = __fmaf_rz(v.w, BINC, FBIAS);

    unsigned a0 = __float_as_uint(f0) * 128u + lanoff2;
    unsigned a1 = __float_as_uint(f1) * 128u + lanoff2;
    unsigned a2 = __float_as_uint(f2) * 128u + lanoff2;
    unsigned a3 = __float_as_uint(f3) * 128u + lanoff2;
    unsigned a4 = __float_as_uint(f4) * 128u + lanoff2;
    unsigned a5 = __float_as_uint(f5) * 128u + lanoff2;
    unsigned a6 = __float_as_uint(f6) * 128u + lanoff2;
    unsigned a7 = __float_as_uint(f7) * 128u + lanoff2;

    unsigned c0 = sh8[a0], c1 = sh8[a1], c2 = sh8[a2], c3 = sh8[a3];
    unsigned c4 = sh8[a4], c5 = sh8[a5], c6 = sh8[a6], c7 = sh8[a7];

    c0 += 1u;
    c1 += 1u + (f1 == f0);
    c2 += 1u + (f2 == f0) + (f2 == f1);
    c3 += 1u + (f3 == f0) + (f3 == f1) + (f3 == f2);
    c4 += 1u + (f4 == f0) + (f4 == f1) + (f4 == f2) + (f4 == f3);
    c5 += 1u + (f5 == f0) + (f5 == f1) + (f5 == f2) + (f5 == f3) + (f5 == f4);
    c6 += 1u + (f6 == f0) + (f6 == f1) + (f6 == f2) + (f6 == f3) + (f6 == f4)
             + (f6 == f5);
    c7 += 1u + (f7 == f0) + (f7 == f1) + (f7 == f2) + (f7 == f3) + (f7 == f4)
             + (f7 == f5) + (f7 == f6);

    sh8[a0] = (unsigned char)c0; sh8[a1] = (unsigned char)c1;
    sh8[a2] = (unsigned char)c2; sh8[a3] = (unsigned char)c3;
    sh8[a4] = (unsigned char)c4; sh8[a5] = (unsigned char)c5;
    sh8[a6] = (unsigned char)c6; sh8[a7] = (unsigned char)c7;
}

__global__ void __launch_bounds__(TPB, 6)
hist_kernel(const float* __restrict__ inf, const int* __restrict__ bsz,
            float* __restrict__ out, int n) {
    __shared__ unsigned int sh[SMEM_WORDS];
    const int t = threadIdx.x;

    #pragma unroll 4
    for (int i = t; i < SMEM_WORDS; i += TPB) sh[i] = 0u;
    __syncthreads();

    unsigned char* sh8 = (unsigned char*)sh;
    // +0x80000000 cancels bits(2^23)*128 mod 2^32 -> addr = bin*128 + lanoff
    const unsigned lanoff2 = (((t & 31) << 2) | (t >> 5)) + 0x80000000u;

    const int n4 = n >> 2;
    const float4* __restrict__ in4 = (const float4*)inf;
    const int S = gridDim.x * TPB;
    int i = blockIdx.x * TPB + t;

    // ---- ping-pong: exactly one pair (2 LDG.128) in flight while the
    //      previous pair's 8 elements are accumulated. Unrolled x2 so the
    //      stage swap costs no register MOVs. ----
    float4 p0, p1, q0, q1;
    if (i + S < n4) {
        p0 = in4[i]; p1 = in4[i + S];
        i += 2 * S;
        while (i + S < n4) {
            q0 = in4[i]; q1 = in4[i + S];      // prefetch B
            acc8(sh8, lanoff2, p0, p1);        // process A (B in flight)
            i += 2 * S;
            if (i + S < n4) {
                p0 = in4[i]; p1 = in4[i + S];  // prefetch A'
                acc8(sh8, lanoff2, q0, q1);    // process B (A' in flight)
                i += 2 * S;
            } else {
                acc8(sh8, lanoff2, q0, q1);
                goto remainder;
            }
        }
        acc8(sh8, lanoff2, p0, p1);            // drain
    }
remainder:
    for (; i < n4; i += S) {                   // float4 remainder
        float4 x = in4[i];
        float f0 = __fmaf_rz(x.x, BINC, FBIAS), f1 = __fmaf_rz(x.y, BINC, FBIAS);
        float f2 = __fmaf_rz(x.z, BINC, FBIAS), f3 = __fmaf_rz(x.w, BINC, FBIAS);
        unsigned a0 = __float_as_uint(f0) * 128u + lanoff2;
        unsigned a1 = __float_as_uint(f1) * 128u + lanoff2;
        unsigned a2 = __float_as_uint(f2) * 128u + lanoff2;
        unsigned a3 = __float_as_uint(f3) * 128u + lanoff2;
        unsigned c0 = sh8[a0], c1 = sh8[a1], c2 = sh8[a2], c3 = sh8[a3];
        c0 += 1u;
        c1 += 1u + (f1 == f0);
        c2 += 1u + (f2 == f0) + (f2 == f1);
        c3 += 1u + (f3 == f0) + (f3 == f1) + (f3 == f2);
        sh8[a0] = (unsigned char)c0; sh8[a1] = (unsigned char)c1;
        sh8[a2] = (unsigned char)c2; sh8[a3] = (unsigned char)c3;
    }
    if (blockIdx.x == 0 && t < (n & 3)) {      // scalar tail
        unsigned a = __float_as_uint(__fmaf_rz(inf[(n4 << 2) + t], BINC, FBIAS))
                     * 128u + lanoff2;
        sh8[a] = (unsigned char)(sh8[a] + 1);
    }
    __syncthreads();

    // per-bin byte-sum via dp4a; one global atomic per bin per block
    for (int b = t; b < 256; b += TPB) {
        unsigned int s = 0;
        #pragma unroll 8
        for (int k = 0; k < WPB; k++)
            s = __dp4a(sh[b * WPB + ((k + t) & (WPB - 1))], 0x01010101u, s);
        atomicAdd(&g_hist[b], s);
    }

    // last arriving block finalizes and resets state (idempotent replays)
    __shared__ unsigned int is_last;
    __shared__ float h0s;
    __threadfence();
    if (t == 0) {
        unsigned ticket = atomicAdd(&g_done, 1u);
        is_last = (ticket == (unsigned)(gridDim.x - 1));
    }
    __syncthreads();
    if (is_last) {
        __threadfence();
        if (t == 0) { h0s = (float)g_hist[0]; g_done = 0u; }
        __syncthreads();
        float c = (float)(*bsz) * h0s;
        #pragma unroll
        for (int b = t; b < 256; b += TPB) {
            out[b]       = (float)g_hist[b];
            out[256 + b] = c;
        }
        __syncthreads();
        #pragma unroll
        for (int b = t; b < 256; b += TPB) g_hist[b] = 0u;
    }
}

extern "C" void kernel_launch(void* const* d_in, const int* in_sizes, int n_in,
                              void* d_out, int out_size) {
    const float* x;
    const int*   bs;
    int n;
    if (n_in >= 2 && in_sizes[0] >= in_sizes[1]) {
        x = (const float*)d_in[0]; bs = (const int*)d_in[1]; n = in_sizes[0];
    } else {
        x = (const float*)d_in[1]; bs = (const int*)d_in[0]; n = in_sizes[1];
    }
    hist_kernel<<<NBLK, TPB>>>(x, bs, (float*)d_out, n);
}